// round 4
// baseline (speedup 1.0000x reference)
#include <cuda_runtime.h>
#include <cuda_fp16.h>
#include <cstdint>

#define NQ 8
#define DIM 256
#define NL 8
#define BATCH 65536

#define TILE_M 64            // samples per CTA
#define THREADS 512          // 16 warps: warp = (mhalf, nchunk)
#define MSTRIDE 264          // m smem row stride in halves (256 + 8 pad)
#define VSTRIDE 40           // V-chunk smem row stride in halves (32 + 8 pad)
#define SMEM_M_BYTES (TILE_M * MSTRIDE * 2)          // 33792
#define SMEM_V_BYTES (512 * VSTRIDE * 2)             // 40960
#define SMEM_TOTAL (SMEM_M_BYTES + SMEM_V_BYTES)     // 74752

// V in fp16, chunked layout: g_Vh[kc][n2][kk], kc=k>>5, kk=k&31, n2 = 2n(+1 for Im)
__device__ __half g_Vh[8 * 512 * 32];

// ---------------------------------------------------------------------------
// Kernel 1: build folded entangler matrix, write fp16 chunked layout.
// ---------------------------------------------------------------------------
__global__ void build_V_kernel(const float* __restrict__ w) {
    __shared__ float2 amp[DIM];
    const int t = threadIdx.x;
    const int k = blockIdx.x;

    amp[t] = make_float2(t == k ? 1.0f : 0.0f, 0.0f);
    __syncthreads();

    for (int l = 0; l < NL; l++) {
        for (int q = 0; q < NQ; q++) {
            const float th_y = w[(l * NQ + q) * 2 + 0];
            const float th_z = w[(l * NQ + q) * 2 + 1];
            const float c  = cosf(0.5f * th_y);
            const float s  = sinf(0.5f * th_y);
            const float zc = cosf(0.5f * th_z);
            const float zs = sinf(0.5f * th_z);
            const int mask = 1 << (7 - q);

            const float2 my    = amp[t];
            const float2 other = amp[t ^ mask];
            __syncthreads();

            float2 r;
            if (!(t & mask)) {
                const float xr = c * my.x - s * other.x;
                const float xi = c * my.y - s * other.y;
                r.x = zc * xr + zs * xi;
                r.y = zc * xi - zs * xr;
            } else {
                const float xr = s * other.x + c * my.x;
                const float xi = s * other.y + c * my.y;
                r.x = zc * xr - zs * xi;
                r.y = zc * xi + zs * xr;
            }
            amp[t] = r;
            __syncthreads();
        }
        for (int q = 0; q < NQ; q++) {
            const int cbit = 1 << (7 - q);
            const int tq   = (q + 1) & 7;
            const int tbit = 1 << (7 - tq);
            const int src  = (t & cbit) ? (t ^ tbit) : t;
            const float2 v = amp[src];
            __syncthreads();
            amp[t] = v;
            __syncthreads();
        }
    }

    const float2 u = amp[t];
    const int pc = __popc(k) & 3;
    float2 vv;
    if      (pc == 0) vv = u;
    else if (pc == 1) vv = make_float2( u.y, -u.x);
    else if (pc == 2) vv = make_float2(-u.x, -u.y);
    else              vv = make_float2(-u.y,  u.x);

    const int kc = k >> 5, kk = k & 31;
    g_Vh[(kc * 512 + 2 * t)     * 32 + kk] = __float2half(vv.x);
    g_Vh[(kc * 512 + 2 * t + 1) * 32 + kk] = __float2half(vv.y);
}

// ---------------------------------------------------------------------------
// Tensor-core helpers
// ---------------------------------------------------------------------------
__device__ __forceinline__ uint32_t smem_u32(const void* p) {
    return (uint32_t)__cvta_generic_to_shared(p);
}

__device__ __forceinline__ void ldsm4(uint32_t r[4], uint32_t addr) {
    asm volatile("ldmatrix.sync.aligned.m8n8.x4.shared.b16 {%0,%1,%2,%3}, [%4];"
                 : "=r"(r[0]), "=r"(r[1]), "=r"(r[2]), "=r"(r[3]) : "r"(addr));
}

__device__ __forceinline__ void mma16816(float4& c, const uint32_t a[4],
                                         uint32_t b0, uint32_t b1) {
    asm volatile(
        "mma.sync.aligned.m16n8k16.row.col.f32.f16.f16.f32 "
        "{%0,%1,%2,%3}, {%4,%5,%6,%7}, {%8,%9}, {%0,%1,%2,%3};"
        : "+f"(c.x), "+f"(c.y), "+f"(c.z), "+f"(c.w)
        : "r"(a[0]), "r"(a[1]), "r"(a[2]), "r"(a[3]), "r"(b0), "r"(b1));
}

// ---------------------------------------------------------------------------
// Kernel 2: fused mma GEMM + epilogue.
//   C[64 samples x 512 cols] = m[64 x 256] * V[256 x 512] in fp16->fp32 mma,
//   cols interleave (Re, Im); prob = Re^2+Im^2; out = signed reductions.
// ---------------------------------------------------------------------------
__global__ __launch_bounds__(THREADS, 1)
void qsim_main_kernel(const float* __restrict__ x, float* __restrict__ out) {
    extern __shared__ __align__(16) char smem_raw[];
    __half* m_sm  = (__half*)smem_raw;                       // [64][MSTRIDE]
    __half* v_sm  = (__half*)(smem_raw + SMEM_M_BYTES);      // [512][VSTRIDE]
    float*  ang   = (float*)(smem_raw + SMEM_M_BYTES);       // overlay: cs/sn
    float*  outSm = (float*)(smem_raw + SMEM_M_BYTES);       // overlay: [64][8]

    const int t  = threadIdx.x;
    const int b0 = blockIdx.x * TILE_M;

    // --- angles: thread -> (s = t>>3, q = t&7), coalesced x load ---
    {
        const int s = t >> 3, q = t & 7;
        const float xv = x[(b0 + s) * NQ + q];
        float sv, cv;
        sincosf(0.5f * xv, &sv, &cv);
        ang[q * 64 + s]       = cv;
        ang[512 + q * 64 + s] = sv;
    }
    __syncthreads();

    // --- build m tile in fp16: thread -> (s = t>>3, kg = t&7), 32 k each ---
    {
        const int s = t >> 3, kg = t & 7;
        float c[NQ], sn[NQ];
#pragma unroll
        for (int q = 0; q < NQ; q++) {
            c[q]  = ang[q * 64 + s];
            sn[q] = ang[512 + q * 64 + s];
        }
        __half* mrow = m_sm + s * MSTRIDE;
#pragma unroll 4
        for (int kk = 0; kk < 32; kk += 2) {
            const int k0 = kg * 32 + kk;
            float mb = 1.0f;
#pragma unroll
            for (int q = 0; q < 7; q++)
                mb *= ((k0 >> (7 - q)) & 1) ? sn[q] : c[q];
            const float m0 = mb * c[7];
            const float m1 = mb * sn[7];
            *(__half2*)(mrow + k0) = __floats2half2_rn(m0, m1);
        }
    }
    // (K-loop top __syncthreads covers m/ang ordering)

    const int warp = t >> 5, lane = t & 31;
    const int mh   = warp & 1;        // which 32-sample half
    const int nch  = warp >> 1;       // n2 chunk of 64: [nch*64, nch*64+64)
    const int gid  = lane >> 2, tig = lane & 3;

    const uint32_t m_u = smem_u32(m_sm);
    const uint32_t v_u = smem_u32(v_sm);

    // ldmatrix per-lane row-address offsets (in halves)
    const int rowA_off = (mh * 32 + (lane & 7) + 8 * ((lane >> 3) & 1)) * MSTRIDE
                       + 8 * (lane >> 4);
    const int rowB_off = (nch * 64 + ((lane >> 4) & 1) * 8 + (lane & 7)) * VSTRIDE
                       + 8 * ((lane >> 3) & 1);

    float4 acc[2][8];
#pragma unroll
    for (int ms = 0; ms < 2; ms++)
#pragma unroll
        for (int nt = 0; nt < 8; nt++)
            acc[ms][nt] = make_float4(0.f, 0.f, 0.f, 0.f);

    // --- K loop: 8 chunks of 32 ---
    for (int kc = 0; kc < 8; kc++) {
        __syncthreads();
        // stage V chunk (32 KB) coalesced from chunked global layout
        const float4* src = (const float4*)(g_Vh + kc * (512 * 32));
#pragma unroll
        for (int j = 0; j < 4; j++) {
            const int e  = t + THREADS * j;   // 0..2047 float4's
            const int n2 = e >> 2, k8 = e & 3;
            *(float4*)(v_sm + n2 * VSTRIDE + k8 * 8) = src[e];
        }
        __syncthreads();

#pragma unroll
        for (int kb = 0; kb < 32; kb += 16) {
            const int kA = kc * 32 + kb;   // <-- FIX: A advances with kc
            uint32_t a[2][4];
            ldsm4(a[0], m_u + (uint32_t)(rowA_off + 0 * 16 * MSTRIDE + kA) * 2u);
            ldsm4(a[1], m_u + (uint32_t)(rowA_off + 1 * 16 * MSTRIDE + kA) * 2u);
#pragma unroll
            for (int nt2 = 0; nt2 < 4; nt2++) {
                uint32_t b[4];
                ldsm4(b, v_u + (uint32_t)(rowB_off + nt2 * 16 * VSTRIDE + kb) * 2u);
                mma16816(acc[0][2 * nt2],     a[0], b[0], b[1]);
                mma16816(acc[0][2 * nt2 + 1], a[0], b[2], b[3]);
                mma16816(acc[1][2 * nt2],     a[1], b[0], b[1]);
                mma16816(acc[1][2 * nt2 + 1], a[1], b[2], b[3]);
            }
        }
    }

    // --- epilogue ---
    __syncthreads();            // all warps done with v_sm
    outSm[t] = 0.0f;            // 512 floats = 64x8
    __syncthreads();

    float aq[2][2][NQ];
#pragma unroll
    for (int ms = 0; ms < 2; ms++)
#pragma unroll
        for (int h = 0; h < 2; h++)
#pragma unroll
            for (int q = 0; q < NQ; q++) aq[ms][h][q] = 0.0f;

#pragma unroll
    for (int ms = 0; ms < 2; ms++) {
#pragma unroll
        for (int nt = 0; nt < 8; nt++) {
            const float4 c = acc[ms][nt];
            const float plo = c.x * c.x + c.y * c.y;   // amplitude row gid
            const float phi = c.z * c.z + c.w * c.w;   // amplitude row gid+8
            const int n = nch * 32 + nt * 4 + tig;     // amplitude index
#pragma unroll
            for (int q = 0; q < NQ; q++) {
                const float sg = ((n >> (7 - q)) & 1) ? -1.0f : 1.0f;
                aq[ms][0][q] += sg * plo;
                aq[ms][1][q] += sg * phi;
            }
        }
    }

#pragma unroll
    for (int ms = 0; ms < 2; ms++)
#pragma unroll
        for (int h = 0; h < 2; h++)
#pragma unroll
            for (int q = 0; q < NQ; q++) {
                float v = aq[ms][h][q];
                v += __shfl_xor_sync(0xffffffffu, v, 1);
                v += __shfl_xor_sync(0xffffffffu, v, 2);
                if (tig == 0) {
                    const int row = mh * 32 + ms * 16 + h * 8 + gid;
                    atomicAdd(&outSm[row * NQ + q], v);
                }
            }

    __syncthreads();
    {
        const int s = t >> 3, q = t & 7;
        out[(b0 + s) * NQ + q] = outSm[t];
    }
}

// ---------------------------------------------------------------------------
extern "C" void kernel_launch(void* const* d_in, const int* in_sizes, int n_in,
                              void* d_out, int out_size) {
    const float* x = (const float*)d_in[0];
    const float* w = (const float*)d_in[1];
    if (n_in >= 2 && in_sizes[0] < in_sizes[1]) {
        const float* tmp = x; x = w; w = tmp;
    }
    float* out = (float*)d_out;

    cudaFuncSetAttribute(qsim_main_kernel,
                         cudaFuncAttributeMaxDynamicSharedMemorySize, SMEM_TOTAL);

    build_V_kernel<<<DIM, DIM>>>(w);
    qsim_main_kernel<<<BATCH / TILE_M, THREADS, SMEM_TOTAL>>>(x, out);
}

// round 5
// speedup vs baseline: 1.0453x; 1.0453x over previous
#include <cuda_runtime.h>
#include <cuda_fp16.h>
#include <cstdint>

#define NQ 8
#define DIM 256
#define BATCH 65536
#define NL 8

#define THREADS 512
#define TILE_M 128
#define NTILES (BATCH / TILE_M)     // 512
#define NPERHALF 74                 // CTAs per N-half; grid = 148
#define STRIDE 264                  // smem row stride in halves (256 + 8 pad)

#define M_BYTES (TILE_M * STRIDE * 2)   // 67584
#define B_OFF   M_BYTES
#define B_BYTES (256 * STRIDE * 2)      // 135168
#define SMEM_TOTAL (M_BYTES + B_BYTES)  // 202752

__device__ __align__(16) __half g_Vtmp[DIM * 2 * DIM];   // [k][n2]  (build output)
__device__ __align__(16) __half g_Vn2k[DIM * 2 * DIM];   // [n2][k]  (GEMM B layout)

// ---------------------------------------------------------------------------
// Kernel 1: build folded entangler matrix -> g_Vtmp[k][n2], coalesced stores.
// ---------------------------------------------------------------------------
__global__ void build_V_kernel(const float* __restrict__ w) {
    __shared__ float2 amp[DIM];
    const int t = threadIdx.x;
    const int k = blockIdx.x;

    amp[t] = make_float2(t == k ? 1.0f : 0.0f, 0.0f);
    __syncthreads();

    for (int l = 0; l < NL; l++) {
        for (int q = 0; q < NQ; q++) {
            const float th_y = w[(l * NQ + q) * 2 + 0];
            const float th_z = w[(l * NQ + q) * 2 + 1];
            const float c  = cosf(0.5f * th_y);
            const float s  = sinf(0.5f * th_y);
            const float zc = cosf(0.5f * th_z);
            const float zs = sinf(0.5f * th_z);
            const int mask = 1 << (7 - q);

            const float2 my    = amp[t];
            const float2 other = amp[t ^ mask];
            __syncthreads();

            float2 r;
            if (!(t & mask)) {
                const float xr = c * my.x - s * other.x;
                const float xi = c * my.y - s * other.y;
                r.x = zc * xr + zs * xi;
                r.y = zc * xi - zs * xr;
            } else {
                const float xr = s * other.x + c * my.x;
                const float xi = s * other.y + c * my.y;
                r.x = zc * xr - zs * xi;
                r.y = zc * xi + zs * xr;
            }
            amp[t] = r;
            __syncthreads();
        }
        for (int q = 0; q < NQ; q++) {
            const int cbit = 1 << (7 - q);
            const int tq   = (q + 1) & 7;
            const int tbit = 1 << (7 - tq);
            const int src  = (t & cbit) ? (t ^ tbit) : t;
            const float2 v = amp[src];
            __syncthreads();
            amp[t] = v;
            __syncthreads();
        }
    }

    const float2 u = amp[t];
    const int pc = __popc(k) & 3;
    float2 vv;
    if      (pc == 0) vv = u;
    else if (pc == 1) vv = make_float2( u.y, -u.x);
    else if (pc == 2) vv = make_float2(-u.x, -u.y);
    else              vv = make_float2(-u.y,  u.x);

    *(__half2*)&g_Vtmp[k * 512 + 2 * t] = __floats2half2_rn(vv.x, vv.y);
}

// ---------------------------------------------------------------------------
// Kernel 2: transpose [k][n2] -> [n2][k] via 32x32 smem tiles.
// ---------------------------------------------------------------------------
__global__ void repack_V_kernel() {
    __shared__ __half tile[32][33];
    const int bk = blockIdx.x & 7;       // k block (8)
    const int bn = blockIdx.x >> 3;      // n2 block (16)
    const int t = threadIdx.x;           // 256
    const int r = t >> 5, c = t & 31;
#pragma unroll
    for (int i = 0; i < 4; i++)
        tile[r + i * 8][c] = g_Vtmp[(bk * 32 + r + i * 8) * 512 + bn * 32 + c];
    __syncthreads();
#pragma unroll
    for (int i = 0; i < 4; i++)
        g_Vn2k[(bn * 32 + r + i * 8) * 256 + bk * 32 + c] = tile[c][r + i * 8];
}

// ---------------------------------------------------------------------------
// Kernel 3: zero output (atomicAdd target).
// ---------------------------------------------------------------------------
__global__ void zero_out_kernel(float4* o) {
    o[blockIdx.x * 256 + threadIdx.x] = make_float4(0.f, 0.f, 0.f, 0.f);
}

// ---------------------------------------------------------------------------
// helpers
// ---------------------------------------------------------------------------
__device__ __forceinline__ uint32_t smem_u32(const void* p) {
    return (uint32_t)__cvta_generic_to_shared(p);
}
__device__ __forceinline__ void cp_async16(uint32_t dst, const void* src) {
    asm volatile("cp.async.cg.shared.global [%0], [%1], 16;" :: "r"(dst), "l"(src));
}
__device__ __forceinline__ void ldsm4(uint32_t r[4], uint32_t addr) {
    asm volatile("ldmatrix.sync.aligned.m8n8.x4.shared.b16 {%0,%1,%2,%3}, [%4];"
                 : "=r"(r[0]), "=r"(r[1]), "=r"(r[2]), "=r"(r[3]) : "r"(addr));
}
__device__ __forceinline__ void mma16816(float4& c, const uint32_t a[4],
                                         uint32_t b0, uint32_t b1) {
    asm volatile(
        "mma.sync.aligned.m16n8k16.row.col.f32.f16.f16.f32 "
        "{%0,%1,%2,%3}, {%4,%5,%6,%7}, {%8,%9}, {%0,%1,%2,%3};"
        : "+f"(c.x), "+f"(c.y), "+f"(c.z), "+f"(c.w)
        : "r"(a[0]), "r"(a[1]), "r"(a[2]), "r"(a[3]), "r"(b0), "r"(b1));
}

// ---------------------------------------------------------------------------
// Kernel 4: persistent GEMM. CTA owns one N-half (B resident in smem),
// loops over sample tiles of 128; per tile: build m, sync-free K=256 mma,
// fused epilogue with global atomicAdd.
// ---------------------------------------------------------------------------
__global__ __launch_bounds__(THREADS, 1)
void qsim_main_kernel(const float* __restrict__ x, float* __restrict__ out) {
    extern __shared__ __align__(16) char smem[];
    __half* m_sm = (__half*)smem;
    float*  comb = (float*)smem;              // overlay on m region (4 KB)

    const int t = threadIdx.x;
    const int warp = t >> 5, lane = t & 31;
    const int half = (blockIdx.x >= NPERHALF) ? 1 : 0;
    const int idx0 = half ? blockIdx.x - NPERHALF : blockIdx.x;

    // ---- stage this CTA's B half (256 n2-rows x 512B) once ----
    {
        const char* src = (const char*)g_Vn2k + half * (256 * 512);
        const uint32_t dst = smem_u32(smem + B_OFF);
#pragma unroll
        for (int i = 0; i < 16; i++) {
            const int e = t + THREADS * i;          // 8192 x 16B
            const int row = e >> 5, c16 = e & 31;
            cp_async16(dst + row * (STRIDE * 2) + c16 * 16,
                       src + row * 512 + c16 * 16);
        }
        asm volatile("cp.async.commit_group;" ::: "memory");
    }

    const uint32_t m_u = smem_u32(m_sm);
    const uint32_t b_u = smem_u32(smem + B_OFF);

    const int mh  = warp >> 3;        // 64-sample half of the tile
    const int nch = warp & 7;         // 32-n2 chunk (16 amplitudes)
    const int gid = lane >> 2, tig = lane & 3;

    const int rowA_off = (mh * 64 + (lane & 7) + 8 * ((lane >> 3) & 1)) * STRIDE
                       + 8 * (lane >> 4);
    const int rowB_off = (nch * 32 + ((lane >> 4) & 1) * 8 + (lane & 7)) * STRIDE
                       + 8 * ((lane >> 3) & 1);

    const int s_mine  = t >> 2;       // sample row this thread builds
    const int kg_mine = t & 3;        // 64-k chunk this thread builds

    bool first = true;
    for (int tile = idx0; tile < NTILES; tile += NPERHALF) {
        __syncthreads();              // prior epilogue done with comb/m region

        // ---- build m tile: m[s][k], fp16 ----
        {
            const float* xp = x + (size_t)(tile * TILE_M + s_mine) * NQ;
            float c[8], sn[8];
#pragma unroll
            for (int q = 0; q < 8; q++) {
                float sv, cv;
                sincosf(0.5f * xp[q], &sv, &cv);
                c[q] = cv; sn[q] = sv;
            }
            // k = kg*64 + kk; bits: q0,q1 from kg; q2,q3 from kk>>4; q4..q7 from kk&15
            const float base2 = ((kg_mine & 2) ? sn[0] : c[0])
                              * ((kg_mine & 1) ? sn[1] : c[1]);
            float B4[4], L16[16];
#pragma unroll
            for (int j = 0; j < 4; j++)
                B4[j] = base2 * ((j & 2) ? sn[2] : c[2]) * ((j & 1) ? sn[3] : c[3]);
#pragma unroll
            for (int v = 0; v < 16; v++)
                L16[v] = ((v & 8) ? sn[4] : c[4]) * ((v & 4) ? sn[5] : c[5])
                       * ((v & 2) ? sn[6] : c[6]) * ((v & 1) ? sn[7] : c[7]);
            __half* mrow = m_sm + s_mine * STRIDE + kg_mine * 64;
#pragma unroll
            for (int kk = 0; kk < 64; kk += 2) {
                const float bb = B4[kk >> 4];
                *(__half2*)(mrow + kk) =
                    __floats2half2_rn(bb * L16[kk & 15], bb * L16[(kk + 1) & 15]);
            }
        }
        if (first) { asm volatile("cp.async.wait_group 0;" ::: "memory"); first = false; }
        __syncthreads();

        // ---- K=256 mma loop, no syncs ----
        float4 acc[4][4];
#pragma unroll
        for (int ms = 0; ms < 4; ms++)
#pragma unroll
            for (int nt = 0; nt < 4; nt++)
                acc[ms][nt] = make_float4(0.f, 0.f, 0.f, 0.f);

#pragma unroll 4
        for (int kb = 0; kb < 256; kb += 16) {
            uint32_t a[4][4], b0[4], b1[4];
#pragma unroll
            for (int ms = 0; ms < 4; ms++)
                ldsm4(a[ms], m_u + (uint32_t)(rowA_off + ms * 16 * STRIDE + kb) * 2u);
            ldsm4(b0, b_u + (uint32_t)(rowB_off + kb) * 2u);
            ldsm4(b1, b_u + (uint32_t)(rowB_off + 16 * STRIDE + kb) * 2u);
#pragma unroll
            for (int ms = 0; ms < 4; ms++) {
                mma16816(acc[ms][0], a[ms], b0[0], b0[1]);
                mma16816(acc[ms][1], a[ms], b0[2], b0[3]);
                mma16816(acc[ms][2], a[ms], b1[0], b1[1]);
                mma16816(acc[ms][3], a[ms], b1[2], b1[3]);
            }
        }

        // ---- epilogue ----
        __syncthreads();                       // all warps done reading m_sm
        if (t < 256) { ((float4*)comb)[t] = make_float4(0.f, 0.f, 0.f, 0.f); }
        __syncthreads();

#pragma unroll
        for (int ms = 0; ms < 4; ms++) {
            float aqlo[8], aqhi[8];
#pragma unroll
            for (int q = 0; q < 8; q++) { aqlo[q] = 0.f; aqhi[q] = 0.f; }
#pragma unroll
            for (int nt = 0; nt < 4; nt++) {
                const float4 cc = acc[ms][nt];
                const float plo = cc.x * cc.x + cc.y * cc.y;
                const float phi = cc.z * cc.z + cc.w * cc.w;
                const int n = half * 128 + nch * 16 + nt * 4 + tig;  // amplitude
#pragma unroll
                for (int q = 0; q < 8; q++) {
                    const uint32_t sgn = (uint32_t)((n >> (7 - q)) & 1) << 31;
                    aqlo[q] += __uint_as_float(__float_as_uint(plo) ^ sgn);
                    aqhi[q] += __uint_as_float(__float_as_uint(phi) ^ sgn);
                }
            }
#pragma unroll
            for (int q = 0; q < 8; q++) {
                float vlo = aqlo[q], vhi = aqhi[q];
                vlo += __shfl_xor_sync(0xffffffffu, vlo, 1);
                vlo += __shfl_xor_sync(0xffffffffu, vlo, 2);
                vhi += __shfl_xor_sync(0xffffffffu, vhi, 1);
                vhi += __shfl_xor_sync(0xffffffffu, vhi, 2);
                if (tig == 0) {
                    const int rbase = mh * 64 + ms * 16;
                    atomicAdd(&comb[(rbase + gid) * 8 + q], vlo);
                    atomicAdd(&comb[(rbase + 8 + gid) * 8 + q], vhi);
                }
            }
        }
        __syncthreads();

        // ---- merge with other N-half via global atomics ----
        {
            const int e0 = t * 2;
            float* op = out + (size_t)(tile * TILE_M) * NQ;
            atomicAdd(&op[e0],     comb[e0]);
            atomicAdd(&op[e0 + 1], comb[e0 + 1]);
        }
    }
}

// ---------------------------------------------------------------------------
extern "C" void kernel_launch(void* const* d_in, const int* in_sizes, int n_in,
                              void* d_out, int out_size) {
    const float* x = (const float*)d_in[0];
    const float* w = (const float*)d_in[1];
    if (n_in >= 2 && in_sizes[0] < in_sizes[1]) {
        const float* tmp = x; x = w; w = tmp;
    }
    float* out = (float*)d_out;

    cudaFuncSetAttribute(qsim_main_kernel,
                         cudaFuncAttributeMaxDynamicSharedMemorySize, SMEM_TOTAL);

    zero_out_kernel<<<512, 256>>>((float4*)out);
    build_V_kernel<<<DIM, DIM>>>(w);
    repack_V_kernel<<<128, 256>>>();
    qsim_main_kernel<<<2 * NPERHALF, THREADS, SMEM_TOTAL>>>(x, out);
}

// round 7
// speedup vs baseline: 1.2898x; 1.2339x over previous
#include <cuda_runtime.h>
#include <cuda_fp16.h>
#include <cstdint>

#define NQ 8
#define DIM 256
#define BATCH 65536
#define NL 8

#define THREADS 256
#define TILE_M 128
#define NTILES (BATCH / TILE_M)     // 512
#define NPERHALF 74                 // grid = 148
#define STRIDE 264                  // smem row stride in halves (256 + 8 pad)

#define M_BYTES (TILE_M * STRIDE * 2)   // 67584
#define B_OFF   M_BYTES
#define B_BYTES (256 * STRIDE * 2)      // 135168
#define SMEM_TOTAL (M_BYTES + B_BYTES)  // 202752

__device__ __align__(16) __half g_Vn2k[512 * 256];   // [n2][k] GEMM B layout

// ---------------------------------------------------------------------------
// Kernel 1: warp-level entangler simulation. One warp = one basis column k.
// State: 256 complex amps in 8 float2 regs/lane, idx = lane*8 + r.
// Wire w -> bit p = 7-w.  p<3: register bit (local);  p>=3: lane bit (shfl).
// No __syncthreads in the simulation. Writes g_Vn2k[n2][k] via smem transpose.
// ---------------------------------------------------------------------------
__global__ void build_V_kernel(const float* __restrict__ w) {
    __shared__ __half tr[8][528];        // [k within block][n2]
    const int t = threadIdx.x;
    const int warp = t >> 5, lane = t & 31;
    const int k = blockIdx.x * 8 + warp;

    float2 a[8];
#pragma unroll
    for (int r = 0; r < 8; r++) {
        const int idx = lane * 8 + r;
        a[r] = make_float2(idx == k ? 1.f : 0.f, 0.f);
    }

    for (int l = 0; l < NL; l++) {
        // RY(th_y) then RZ(th_z) on each wire
#pragma unroll
        for (int q = 0; q < 8; q++) {
            float s, c, zs, zc;
            __sincosf(0.5f * w[(l * 8 + q) * 2 + 0], &s, &c);
            __sincosf(0.5f * w[(l * 8 + q) * 2 + 1], &zs, &zc);
            const int p = 7 - q;
            if (p < 3) {
                const int bit = 1 << p;
#pragma unroll
                for (int r = 0; r < 8; r++) {
                    if (!(r & bit)) {
                        const float2 a0 = a[r], a1 = a[r | bit];
                        const float xr0 = c * a0.x - s * a1.x;
                        const float xi0 = c * a0.y - s * a1.y;
                        const float xr1 = s * a0.x + c * a1.x;
                        const float xi1 = s * a0.y + c * a1.y;
                        a[r]       = make_float2(zc * xr0 + zs * xi0, zc * xi0 - zs * xr0);
                        a[r | bit] = make_float2(zc * xr1 - zs * xi1, zc * xi1 + zs * xr1);
                    }
                }
            } else {
                const int lm = 1 << (p - 3);
                const bool hi = (lane & lm) != 0;
                const float zss = hi ? -zs : zs;
#pragma unroll
                for (int r = 0; r < 8; r++) {
                    const float ox = __shfl_xor_sync(0xffffffffu, a[r].x, lm);
                    const float oy = __shfl_xor_sync(0xffffffffu, a[r].y, lm);
                    const float xr = hi ? (s * ox + c * a[r].x) : (c * a[r].x - s * ox);
                    const float xi = hi ? (s * oy + c * a[r].y) : (c * a[r].y - s * oy);
                    a[r] = make_float2(zc * xr + zss * xi, zc * xi - zss * xr);
                }
            }
        }
        // CNOT ring: control wire q (bit 7-q), target wire (q+1)%8.
        // amp'[i] = amp[i ^ tbit] iff control bit of i set.
#pragma unroll
        for (int q = 0; q < 8; q++) {
            const int cp = 7 - q, tp = 7 - ((q + 1) & 7);
            if (cp >= 3 && tp >= 3) {
                const int cl = 1 << (cp - 3), tl = 1 << (tp - 3);
#pragma unroll
                for (int r = 0; r < 8; r++) {
                    const float ox = __shfl_xor_sync(0xffffffffu, a[r].x, tl);
                    const float oy = __shfl_xor_sync(0xffffffffu, a[r].y, tl);
                    if (lane & cl) { a[r].x = ox; a[r].y = oy; }
                }
            } else if (cp >= 3) {          // lane control, register target
                const int cl = 1 << (cp - 3), tb = 1 << tp;
                if (lane & cl) {
#pragma unroll
                    for (int r = 0; r < 8; r++) {
                        if (!(r & tb)) {
                            const float2 tmp = a[r]; a[r] = a[r | tb]; a[r | tb] = tmp;
                        }
                    }
                }
            } else if (tp >= 3) {          // register control, lane target
                const int cb = 1 << cp, tl = 1 << (tp - 3);
#pragma unroll
                for (int r = 0; r < 8; r++) {
                    const float ox = __shfl_xor_sync(0xffffffffu, a[r].x, tl);
                    const float oy = __shfl_xor_sync(0xffffffffu, a[r].y, tl);
                    if (r & cb) { a[r].x = ox; a[r].y = oy; }
                }
            } else {                       // both register bits
                const int cb = 1 << cp, tb = 1 << tp;
#pragma unroll
                for (int r = 0; r < 8; r++) {
                    if ((r & cb) && !(r & tb)) {
                        const float2 tmp = a[r]; a[r] = a[r | tb]; a[r | tb] = tmp;
                    }
                }
            }
        }
    }

    // fold embedding phase (-i)^popcount(k), deposit into smem transpose buf
    const int pc = __popc(k) & 3;
#pragma unroll
    for (int r = 0; r < 8; r++) {
        const float2 u = a[r];
        float2 vv;
        if      (pc == 0) vv = u;
        else if (pc == 1) vv = make_float2( u.y, -u.x);
        else if (pc == 2) vv = make_float2(-u.x, -u.y);
        else              vv = make_float2(-u.y,  u.x);
        const int n2 = (lane * 8 + r) * 2;
        *(__half2*)&tr[warp][n2] = __floats2half2_rn(vv.x, vv.y);
    }
    __syncthreads();

    // write out: thread t -> n2 rows 2t, 2t+1; 16B (8 k-halves) per row
    const int kb = blockIdx.x * 8;
#pragma unroll
    for (int i = 0; i < 2; i++) {
        const int n2 = 2 * t + i;
        __half tmp[8];
#pragma unroll
        for (int kk = 0; kk < 8; kk++) tmp[kk] = tr[kk][n2];
        *(uint4*)&g_Vn2k[n2 * 256 + kb] = *(uint4*)tmp;
    }
}

// ---------------------------------------------------------------------------
// Kernel 2: zero output (atomicAdd target).
// ---------------------------------------------------------------------------
__global__ void zero_out_kernel(float4* o) {
    o[blockIdx.x * 256 + threadIdx.x] = make_float4(0.f, 0.f, 0.f, 0.f);
}

// ---------------------------------------------------------------------------
// helpers
// ---------------------------------------------------------------------------
__device__ __forceinline__ uint32_t smem_u32(const void* p) {
    return (uint32_t)__cvta_generic_to_shared(p);
}
__device__ __forceinline__ void cp_async16(uint32_t dst, const void* src) {
    asm volatile("cp.async.cg.shared.global [%0], [%1], 16;" :: "r"(dst), "l"(src));
}
__device__ __forceinline__ void ldsm4(uint32_t r[4], uint32_t addr) {
    asm volatile("ldmatrix.sync.aligned.m8n8.x4.shared.b16 {%0,%1,%2,%3}, [%4];"
                 : "=r"(r[0]), "=r"(r[1]), "=r"(r[2]), "=r"(r[3]) : "r"(addr));
}
__device__ __forceinline__ void mma16816(float4& c, const uint32_t a[4],
                                         uint32_t b0, uint32_t b1) {
    asm volatile(
        "mma.sync.aligned.m16n8k16.row.col.f32.f16.f16.f32 "
        "{%0,%1,%2,%3}, {%4,%5,%6,%7}, {%8,%9}, {%0,%1,%2,%3};"
        : "+f"(c.x), "+f"(c.y), "+f"(c.z), "+f"(c.w)
        : "r"(a[0]), "r"(a[1]), "r"(a[2]), "r"(a[3]), "r"(b0), "r"(b1));
}

// ---------------------------------------------------------------------------
// Kernel 3: persistent GEMM. 8 warps, warp tile 64 samples x 64 n2
// (minimizes ldmatrix traffic: 1/64+1/64 vs 1/64+1/32 before).
// CTA owns one N-half (B resident in smem). Per tile: build m, K=256
// sync-free mma loop, fused epilogue with global atomicAdd.
// ---------------------------------------------------------------------------
__global__ __launch_bounds__(THREADS, 1)
void qsim_main_kernel(const float* __restrict__ x, float* __restrict__ out) {
    extern __shared__ __align__(16) char smem[];
    __half* m_sm = (__half*)smem;
    float*  comb = (float*)smem;            // overlay on m region (4 KB)

    const int t = threadIdx.x;
    const int warp = t >> 5, lane = t & 31;
    const int half = (blockIdx.x >= NPERHALF) ? 1 : 0;
    const int idx0 = half ? (int)blockIdx.x - NPERHALF : (int)blockIdx.x;

    // ---- stage this CTA's B half (256 n2-rows x 512B) once ----
    {
        const char* src = (const char*)g_Vn2k + half * (256 * 512);
        const uint32_t dst = smem_u32(smem + B_OFF);
#pragma unroll
        for (int i = 0; i < 32; i++) {
            const int e = t + THREADS * i;          // 8192 x 16B
            const int row = e >> 5, c16 = e & 31;
            cp_async16(dst + row * (STRIDE * 2) + c16 * 16,
                       src + row * 512 + c16 * 16);
        }
        asm volatile("cp.async.commit_group;" ::: "memory");
    }

    const uint32_t m_u = smem_u32(m_sm);
    const uint32_t b_u = smem_u32(smem + B_OFF);

    const int mh  = warp >> 2;        // 64-sample half of the tile
    const int nch = warp & 3;         // 64-n2 chunk (32 amplitudes)
    const int gid = lane >> 2, tig = lane & 3;

    const int rowA_off = (mh * 64 + (lane & 7) + 8 * ((lane >> 3) & 1)) * STRIDE
                       + 8 * (lane >> 4);
    const int rowB_off = (nch * 64 + ((lane >> 4) & 1) * 8 + (lane & 7)) * STRIDE
                       + 8 * ((lane >> 3) & 1);

    const int s_mine  = t >> 1;       // sample row this thread builds
    const int kg_mine = t & 1;        // 128-k chunk this thread builds

    bool first = true;
    for (int tile = idx0; tile < NTILES; tile += NPERHALF) {
        __syncthreads();              // prior epilogue done with comb/m region

        // ---- build m tile: m[s][k], fp16; k = kg*128 + kk ----
        // bits: q0 <- kg; q1..q3 <- kk>>4; q4..q7 <- kk&15
        {
            const float* xp = x + (size_t)(tile * TILE_M + s_mine) * NQ;
            float c[8], sn[8];
#pragma unroll
            for (int q = 0; q < 8; q++) {
                float sv, cv;
                __sincosf(0.5f * xp[q], &sv, &cv);
                c[q] = cv; sn[q] = sv;
            }
            const float base1 = kg_mine ? sn[0] : c[0];
            float H8[8], L16[16];
#pragma unroll
            for (int j = 0; j < 8; j++)
                H8[j] = base1 * ((j & 4) ? sn[1] : c[1]) * ((j & 2) ? sn[2] : c[2])
                      * ((j & 1) ? sn[3] : c[3]);
#pragma unroll
            for (int v = 0; v < 16; v++)
                L16[v] = ((v & 8) ? sn[4] : c[4]) * ((v & 4) ? sn[5] : c[5])
                       * ((v & 2) ? sn[6] : c[6]) * ((v & 1) ? sn[7] : c[7]);
            __half* mrow = m_sm + s_mine * STRIDE + kg_mine * 128;
#pragma unroll
            for (int kk = 0; kk < 128; kk += 8) {
                const float hh = H8[kk >> 4];
                __half tmp[8];
#pragma unroll
                for (int e = 0; e < 8; e += 2) {
                    const __half2 h2 = __floats2half2_rn(hh * L16[(kk + e) & 15],
                                                         hh * L16[(kk + e + 1) & 15]);
                    *(__half2*)&tmp[e] = h2;
                }
                *(uint4*)(mrow + kk) = *(uint4*)tmp;
            }
        }
        if (first) { asm volatile("cp.async.wait_group 0;" ::: "memory"); first = false; }
        __syncthreads();

        // ---- K=256 mma loop, no syncs; 8 ldsm4 -> 32 HMMA per k16 ----
        float4 acc[4][8];
#pragma unroll
        for (int ms = 0; ms < 4; ms++)
#pragma unroll
            for (int nt = 0; nt < 8; nt++)
                acc[ms][nt] = make_float4(0.f, 0.f, 0.f, 0.f);

#pragma unroll 2
        for (int kb = 0; kb < 256; kb += 16) {
            uint32_t a[4][4], b[4][4];
#pragma unroll
            for (int ms = 0; ms < 4; ms++)
                ldsm4(a[ms], m_u + (uint32_t)(rowA_off + ms * 16 * STRIDE + kb) * 2u);
#pragma unroll
            for (int j = 0; j < 4; j++)
                ldsm4(b[j], b_u + (uint32_t)(rowB_off + j * 16 * STRIDE + kb) * 2u);
#pragma unroll
            for (int ms = 0; ms < 4; ms++) {
#pragma unroll
                for (int j = 0; j < 4; j++) {
                    mma16816(acc[ms][2 * j],     a[ms], b[j][0], b[j][1]);
                    mma16816(acc[ms][2 * j + 1], a[ms], b[j][2], b[j][3]);
                }
            }
        }

        // ---- epilogue ----
        __syncthreads();                       // all warps done reading m_sm
        ((float4*)comb)[t] = make_float4(0.f, 0.f, 0.f, 0.f);   // 128x8 floats
        __syncthreads();

#pragma unroll
        for (int ms = 0; ms < 4; ms++) {
            float aqlo[8], aqhi[8];
#pragma unroll
            for (int q = 0; q < 8; q++) { aqlo[q] = 0.f; aqhi[q] = 0.f; }
#pragma unroll
            for (int nt = 0; nt < 8; nt++) {
                const float4 cc = acc[ms][nt];
                const float plo = cc.x * cc.x + cc.y * cc.y;
                const float phi = cc.z * cc.z + cc.w * cc.w;
                const int n = half * 128 + nch * 32 + nt * 4 + tig;  // amplitude
#pragma unroll
                for (int q = 0; q < 8; q++) {
                    const uint32_t sgn = (uint32_t)((n >> (7 - q)) & 1) << 31;
                    aqlo[q] += __uint_as_float(__float_as_uint(plo) ^ sgn);
                    aqhi[q] += __uint_as_float(__float_as_uint(phi) ^ sgn);
                }
            }
#pragma unroll
            for (int q = 0; q < 8; q++) {
                float vlo = aqlo[q], vhi = aqhi[q];
                vlo += __shfl_xor_sync(0xffffffffu, vlo, 1);
                vlo += __shfl_xor_sync(0xffffffffu, vlo, 2);
                vhi += __shfl_xor_sync(0xffffffffu, vhi, 1);
                vhi += __shfl_xor_sync(0xffffffffu, vhi, 2);
                if (tig == 0) {
                    const int rbase = mh * 64 + ms * 16;
                    atomicAdd(&comb[(rbase + gid) * 8 + q], vlo);
                    atomicAdd(&comb[(rbase + 8 + gid) * 8 + q], vhi);
                }
            }
        }
        __syncthreads();

        // ---- merge with other N-half via global atomics (4 per thread) ----
        {
            const int rr = t >> 1, qp = (t & 1) * 4;
            const float* cp2 = comb + rr * 8 + qp;
            float* op = out + (size_t)(tile * TILE_M + rr) * NQ + qp;
            atomicAdd(op,     cp2[0]);
            atomicAdd(op + 1, cp2[1]);
            atomicAdd(op + 2, cp2[2]);
            atomicAdd(op + 3, cp2[3]);
        }
    }
}

// ---------------------------------------------------------------------------
extern "C" void kernel_launch(void* const* d_in, const int* in_sizes, int n_in,
                              void* d_out, int out_size) {
    const float* x = (const float*)d_in[0];
    const float* w = (const float*)d_in[1];
    if (n_in >= 2 && in_sizes[0] < in_sizes[1]) {
        const float* tmp = x; x = w; w = tmp;
    }
    float* out = (float*)d_out;

    cudaFuncSetAttribute(qsim_main_kernel,
                         cudaFuncAttributeMaxDynamicSharedMemorySize, SMEM_TOTAL);

    zero_out_kernel<<<512, 256>>>((float4*)out);
    build_V_kernel<<<32, 256>>>(w);
    qsim_main_kernel<<<2 * NPERHALF, THREADS, SMEM_TOTAL>>>(x, out);
}

// round 8
// speedup vs baseline: 1.2945x; 1.0037x over previous
#include <cuda_runtime.h>
#include <cuda_fp16.h>
#include <cstdint>

#define NQ 8
#define DIM 256
#define BATCH 65536
#define NL 8

#define THREADS 256
#define TILE_M 128
#define NTILES (BATCH / TILE_M)     // 512
#define NPERHALF 74                 // grid = 148
#define STRIDE 264                  // smem row stride in halves (256 + 8 pad)

#define M_BYTES (TILE_M * STRIDE * 2)   // 67584
#define B_OFF   M_BYTES
#define B_BYTES (256 * STRIDE * 2)      // 135168
#define SMEM_TOTAL (M_BYTES + B_BYTES)  // 202752

__device__ __align__(16) __half g_Vn2k[512 * 256];   // [n2][k] GEMM B layout

// ---------------------------------------------------------------------------
// Kernel 1: blocks 0..31 = warp-level entangler simulation (one warp = one
// basis column k; no __syncthreads in the sim). Blocks 32..543 zero out[].
// ---------------------------------------------------------------------------
__global__ void build_V_kernel(const float* __restrict__ w, float4* __restrict__ out4) {
    if (blockIdx.x >= 32) {
        out4[(blockIdx.x - 32) * 256 + threadIdx.x] = make_float4(0.f, 0.f, 0.f, 0.f);
        return;
    }
    __shared__ __half tr[8][528];        // [k within block][n2]
    const int t = threadIdx.x;
    const int warp = t >> 5, lane = t & 31;
    const int k = blockIdx.x * 8 + warp;

    float2 a[8];
#pragma unroll
    for (int r = 0; r < 8; r++) {
        const int idx = lane * 8 + r;
        a[r] = make_float2(idx == k ? 1.f : 0.f, 0.f);
    }

    for (int l = 0; l < NL; l++) {
#pragma unroll
        for (int q = 0; q < 8; q++) {
            float s, c, zs, zc;
            __sincosf(0.5f * w[(l * 8 + q) * 2 + 0], &s, &c);
            __sincosf(0.5f * w[(l * 8 + q) * 2 + 1], &zs, &zc);
            const int p = 7 - q;
            if (p < 3) {
                const int bit = 1 << p;
#pragma unroll
                for (int r = 0; r < 8; r++) {
                    if (!(r & bit)) {
                        const float2 a0 = a[r], a1 = a[r | bit];
                        const float xr0 = c * a0.x - s * a1.x;
                        const float xi0 = c * a0.y - s * a1.y;
                        const float xr1 = s * a0.x + c * a1.x;
                        const float xi1 = s * a0.y + c * a1.y;
                        a[r]       = make_float2(zc * xr0 + zs * xi0, zc * xi0 - zs * xr0);
                        a[r | bit] = make_float2(zc * xr1 - zs * xi1, zc * xi1 + zs * xr1);
                    }
                }
            } else {
                const int lm = 1 << (p - 3);
                const bool hi = (lane & lm) != 0;
                const float zss = hi ? -zs : zs;
#pragma unroll
                for (int r = 0; r < 8; r++) {
                    const float ox = __shfl_xor_sync(0xffffffffu, a[r].x, lm);
                    const float oy = __shfl_xor_sync(0xffffffffu, a[r].y, lm);
                    const float xr = hi ? (s * ox + c * a[r].x) : (c * a[r].x - s * ox);
                    const float xi = hi ? (s * oy + c * a[r].y) : (c * a[r].y - s * oy);
                    a[r] = make_float2(zc * xr + zss * xi, zc * xi - zss * xr);
                }
            }
        }
#pragma unroll
        for (int q = 0; q < 8; q++) {
            const int cp = 7 - q, tp = 7 - ((q + 1) & 7);
            if (cp >= 3 && tp >= 3) {
                const int cl = 1 << (cp - 3), tl = 1 << (tp - 3);
#pragma unroll
                for (int r = 0; r < 8; r++) {
                    const float ox = __shfl_xor_sync(0xffffffffu, a[r].x, tl);
                    const float oy = __shfl_xor_sync(0xffffffffu, a[r].y, tl);
                    if (lane & cl) { a[r].x = ox; a[r].y = oy; }
                }
            } else if (cp >= 3) {
                const int cl = 1 << (cp - 3), tb = 1 << tp;
                if (lane & cl) {
#pragma unroll
                    for (int r = 0; r < 8; r++) {
                        if (!(r & tb)) {
                            const float2 tmp = a[r]; a[r] = a[r | tb]; a[r | tb] = tmp;
                        }
                    }
                }
            } else if (tp >= 3) {
                const int cb = 1 << cp, tl = 1 << (tp - 3);
#pragma unroll
                for (int r = 0; r < 8; r++) {
                    const float ox = __shfl_xor_sync(0xffffffffu, a[r].x, tl);
                    const float oy = __shfl_xor_sync(0xffffffffu, a[r].y, tl);
                    if (r & cb) { a[r].x = ox; a[r].y = oy; }
                }
            } else {
                const int cb = 1 << cp, tb = 1 << tp;
#pragma unroll
                for (int r = 0; r < 8; r++) {
                    if ((r & cb) && !(r & tb)) {
                        const float2 tmp = a[r]; a[r] = a[r | tb]; a[r | tb] = tmp;
                    }
                }
            }
        }
    }

    const int pc = __popc(k) & 3;
#pragma unroll
    for (int r = 0; r < 8; r++) {
        const float2 u = a[r];
        float2 vv;
        if      (pc == 0) vv = u;
        else if (pc == 1) vv = make_float2( u.y, -u.x);
        else if (pc == 2) vv = make_float2(-u.x, -u.y);
        else              vv = make_float2(-u.y,  u.x);
        const int n2 = (lane * 8 + r) * 2;
        *(__half2*)&tr[warp][n2] = __floats2half2_rn(vv.x, vv.y);
    }
    __syncthreads();

    const int kb = blockIdx.x * 8;
#pragma unroll
    for (int i = 0; i < 2; i++) {
        const int n2 = 2 * t + i;
        __half tmp[8];
#pragma unroll
        for (int kk = 0; kk < 8; kk++) tmp[kk] = tr[kk][n2];
        *(uint4*)&g_Vn2k[n2 * 256 + kb] = *(uint4*)tmp;
    }
}

// ---------------------------------------------------------------------------
// helpers
// ---------------------------------------------------------------------------
__device__ __forceinline__ uint32_t smem_u32(const void* p) {
    return (uint32_t)__cvta_generic_to_shared(p);
}
__device__ __forceinline__ void cp_async16(uint32_t dst, const void* src) {
    asm volatile("cp.async.cg.shared.global [%0], [%1], 16;" :: "r"(dst), "l"(src));
}
__device__ __forceinline__ void ldsm4(uint32_t r[4], uint32_t addr) {
    asm volatile("ldmatrix.sync.aligned.m8n8.x4.shared.b16 {%0,%1,%2,%3}, [%4];"
                 : "=r"(r[0]), "=r"(r[1]), "=r"(r[2]), "=r"(r[3]) : "r"(addr));
}
__device__ __forceinline__ void mma16816(float4& c, const uint32_t a[4],
                                         uint32_t b0, uint32_t b1) {
    asm volatile(
        "mma.sync.aligned.m16n8k16.row.col.f32.f16.f16.f32 "
        "{%0,%1,%2,%3}, {%4,%5,%6,%7}, {%8,%9}, {%0,%1,%2,%3};"
        : "+f"(c.x), "+f"(c.y), "+f"(c.z), "+f"(c.w)
        : "r"(a[0]), "r"(a[1]), "r"(a[2]), "r"(a[3]), "r"(b0), "r"(b1));
}

// ---------------------------------------------------------------------------
// Kernel 2: persistent GEMM. 8 warps, warp tile 64 samples x 64 n2.
// K-loop uses explicit 2-deep register fragment double-buffering so LDSM for
// step i+1 hides under the 32 HMMAs of step i.
// ---------------------------------------------------------------------------
__global__ __launch_bounds__(THREADS, 1)
void qsim_main_kernel(const float* __restrict__ x, float* __restrict__ out) {
    extern __shared__ __align__(16) char smem[];
    __half* m_sm = (__half*)smem;
    float*  comb = (float*)smem;            // overlay on m region (4 KB)

    const int t = threadIdx.x;
    const int warp = t >> 5, lane = t & 31;
    const int half = (blockIdx.x >= NPERHALF) ? 1 : 0;
    const int idx0 = half ? (int)blockIdx.x - NPERHALF : (int)blockIdx.x;

    // ---- stage this CTA's B half once ----
    {
        const char* src = (const char*)g_Vn2k + half * (256 * 512);
        const uint32_t dst = smem_u32(smem + B_OFF);
#pragma unroll
        for (int i = 0; i < 32; i++) {
            const int e = t + THREADS * i;
            const int row = e >> 5, c16 = e & 31;
            cp_async16(dst + row * (STRIDE * 2) + c16 * 16,
                       src + row * 512 + c16 * 16);
        }
        asm volatile("cp.async.commit_group;" ::: "memory");
    }

    const uint32_t m_u = smem_u32(m_sm);
    const uint32_t b_u = smem_u32(smem + B_OFF);

    const int mh  = warp >> 2;
    const int nch = warp & 3;
    const int gid = lane >> 2, tig = lane & 3;

    const int rowA_off = (mh * 64 + (lane & 7) + 8 * ((lane >> 3) & 1)) * STRIDE
                       + 8 * (lane >> 4);
    const int rowB_off = (nch * 64 + ((lane >> 4) & 1) * 8 + (lane & 7)) * STRIDE
                       + 8 * ((lane >> 3) & 1);

    const int s_mine  = t >> 1;
    const int kg_mine = t & 1;

    bool first = true;
    for (int tile = idx0; tile < NTILES; tile += NPERHALF) {
        // prefetch angles for this tile before the barrier
        float xv[8];
        {
            const float* xp = x + (size_t)(tile * TILE_M + s_mine) * NQ;
#pragma unroll
            for (int q = 0; q < 8; q++) xv[q] = xp[q];
        }
        __syncthreads();              // prior epilogue done with comb/m region

        // ---- build m tile ----
        {
            float c[8], sn[8];
#pragma unroll
            for (int q = 0; q < 8; q++) {
                float sv, cv;
                __sincosf(0.5f * xv[q], &sv, &cv);
                c[q] = cv; sn[q] = sv;
            }
            const float base1 = kg_mine ? sn[0] : c[0];
            float H8[8], L16[16];
#pragma unroll
            for (int j = 0; j < 8; j++)
                H8[j] = base1 * ((j & 4) ? sn[1] : c[1]) * ((j & 2) ? sn[2] : c[2])
                      * ((j & 1) ? sn[3] : c[3]);
#pragma unroll
            for (int v = 0; v < 16; v++)
                L16[v] = ((v & 8) ? sn[4] : c[4]) * ((v & 4) ? sn[5] : c[5])
                       * ((v & 2) ? sn[6] : c[6]) * ((v & 1) ? sn[7] : c[7]);
            __half* mrow = m_sm + s_mine * STRIDE + kg_mine * 128;
#pragma unroll
            for (int kk = 0; kk < 128; kk += 8) {
                const float hh = H8[kk >> 4];
                __half tmp[8];
#pragma unroll
                for (int e = 0; e < 8; e += 2) {
                    const __half2 h2 = __floats2half2_rn(hh * L16[(kk + e) & 15],
                                                         hh * L16[(kk + e + 1) & 15]);
                    *(__half2*)&tmp[e] = h2;
                }
                *(uint4*)(mrow + kk) = *(uint4*)tmp;
            }
        }
        if (first) { asm volatile("cp.async.wait_group 0;" ::: "memory"); first = false; }
        __syncthreads();

        // ---- K=256 mma loop with register double-buffered fragments ----
        float4 acc[4][8];
#pragma unroll
        for (int ms = 0; ms < 4; ms++)
#pragma unroll
            for (int nt = 0; nt < 8; nt++)
                acc[ms][nt] = make_float4(0.f, 0.f, 0.f, 0.f);

        uint32_t aF[2][4][4], bF[2][4][4];
#pragma unroll
        for (int ms = 0; ms < 4; ms++)
            ldsm4(aF[0][ms], m_u + (uint32_t)(rowA_off + ms * 16 * STRIDE) * 2u);
#pragma unroll
        for (int j = 0; j < 4; j++)
            ldsm4(bF[0][j], b_u + (uint32_t)(rowB_off + j * 16 * STRIDE) * 2u);

#pragma unroll
        for (int it = 0; it < 16; it++) {
            const int p = it & 1;
            if (it < 15) {
                const int kb = (it + 1) * 16;
#pragma unroll
                for (int ms = 0; ms < 4; ms++)
                    ldsm4(aF[p ^ 1][ms],
                          m_u + (uint32_t)(rowA_off + ms * 16 * STRIDE + kb) * 2u);
#pragma unroll
                for (int j = 0; j < 4; j++)
                    ldsm4(bF[p ^ 1][j],
                          b_u + (uint32_t)(rowB_off + j * 16 * STRIDE + kb) * 2u);
            }
#pragma unroll
            for (int ms = 0; ms < 4; ms++) {
#pragma unroll
                for (int j = 0; j < 4; j++) {
                    mma16816(acc[ms][2 * j],     aF[p][ms], bF[p][j][0], bF[p][j][1]);
                    mma16816(acc[ms][2 * j + 1], aF[p][ms], bF[p][j][2], bF[p][j][3]);
                }
            }
        }

        // ---- epilogue ----
        __syncthreads();
        ((float4*)comb)[t] = make_float4(0.f, 0.f, 0.f, 0.f);
        __syncthreads();

#pragma unroll
        for (int ms = 0; ms < 4; ms++) {
            float aqlo[8], aqhi[8];
#pragma unroll
            for (int q = 0; q < 8; q++) { aqlo[q] = 0.f; aqhi[q] = 0.f; }
#pragma unroll
            for (int nt = 0; nt < 8; nt++) {
                const float4 cc = acc[ms][nt];
                const float plo = cc.x * cc.x + cc.y * cc.y;
                const float phi = cc.z * cc.z + cc.w * cc.w;
                const int n = half * 128 + nch * 32 + nt * 4 + tig;
#pragma unroll
                for (int q = 0; q < 8; q++) {
                    const uint32_t sgn = (uint32_t)((n >> (7 - q)) & 1) << 31;
                    aqlo[q] += __uint_as_float(__float_as_uint(plo) ^ sgn);
                    aqhi[q] += __uint_as_float(__float_as_uint(phi) ^ sgn);
                }
            }
#pragma unroll
            for (int q = 0; q < 8; q++) {
                float vlo = aqlo[q], vhi = aqhi[q];
                vlo += __shfl_xor_sync(0xffffffffu, vlo, 1);
                vlo += __shfl_xor_sync(0xffffffffu, vlo, 2);
                vhi += __shfl_xor_sync(0xffffffffu, vhi, 1);
                vhi += __shfl_xor_sync(0xffffffffu, vhi, 2);
                if (tig == 0) {
                    const int rbase = mh * 64 + ms * 16;
                    atomicAdd(&comb[(rbase + gid) * 8 + q], vlo);
                    atomicAdd(&comb[(rbase + 8 + gid) * 8 + q], vhi);
                }
            }
        }
        __syncthreads();

        {
            const int rr = t >> 1, qp = (t & 1) * 4;
            const float* cp2 = comb + rr * 8 + qp;
            float* op = out + (size_t)(tile * TILE_M + rr) * NQ + qp;
            atomicAdd(op,     cp2[0]);
            atomicAdd(op + 1, cp2[1]);
            atomicAdd(op + 2, cp2[2]);
            atomicAdd(op + 3, cp2[3]);
        }
    }
}

// ---------------------------------------------------------------------------
extern "C" void kernel_launch(void* const* d_in, const int* in_sizes, int n_in,
                              void* d_out, int out_size) {
    const float* x = (const float*)d_in[0];
    const float* w = (const float*)d_in[1];
    if (n_in >= 2 && in_sizes[0] < in_sizes[1]) {
        const float* tmp = x; x = w; w = tmp;
    }
    float* out = (float*)d_out;

    cudaFuncSetAttribute(qsim_main_kernel,
                         cudaFuncAttributeMaxDynamicSharedMemorySize, SMEM_TOTAL);

    build_V_kernel<<<544, 256>>>(w, (float4*)out);
    qsim_main_kernel<<<2 * NPERHALF, THREADS, SMEM_TOTAL>>>(x, out);
}

// round 10
// speedup vs baseline: 1.7283x; 1.3351x over previous
#include <cuda_runtime.h>
#include <cuda_fp16.h>
#include <cstdint>

#define NQ 8
#define DIM 256
#define BATCH 65536
#define NL 8

#define THREADS 128
#define TILE_M 64
#define NTILES (BATCH / TILE_M)     // 1024
#define NPERQ 74                    // CTAs per N-quarter; grid = 296 (2/SM)
#define STRIDE 264                  // smem row stride in halves (256 + 8 pad)

#define M_BYTES (TILE_M * STRIDE * 2)   // 33792
#define B_OFF   M_BYTES
#define B_BYTES (128 * STRIDE * 2)      // 67584
#define SMEM_TOTAL (M_BYTES + B_BYTES)  // 101376  (2 CTAs = 202752 < 228K)

__device__ __align__(16) __half g_Vn2k[512 * 256];   // [n2][k] GEMM B layout

// ---------------------------------------------------------------------------
// Kernel 1: blocks 0..31 = warp-level entangler simulation (one warp = one
// basis column k). Blocks 32..543 zero out[].
// ---------------------------------------------------------------------------
__global__ void build_V_kernel(const float* __restrict__ w, float4* __restrict__ out4) {
    if (blockIdx.x >= 32) {
        out4[(blockIdx.x - 32) * 256 + threadIdx.x] = make_float4(0.f, 0.f, 0.f, 0.f);
        return;
    }
    __shared__ __half tr[8][528];        // [k within block][n2]
    const int t = threadIdx.x;
    const int warp = t >> 5, lane = t & 31;
    const int k = blockIdx.x * 8 + warp;

    float2 a[8];
#pragma unroll
    for (int r = 0; r < 8; r++) {
        const int idx = lane * 8 + r;
        a[r] = make_float2(idx == k ? 1.f : 0.f, 0.f);
    }

    for (int l = 0; l < NL; l++) {
#pragma unroll
        for (int q = 0; q < 8; q++) {
            float s, c, zs, zc;
            __sincosf(0.5f * w[(l * 8 + q) * 2 + 0], &s, &c);
            __sincosf(0.5f * w[(l * 8 + q) * 2 + 1], &zs, &zc);
            const int p = 7 - q;
            if (p < 3) {
                const int bit = 1 << p;
#pragma unroll
                for (int r = 0; r < 8; r++) {
                    if (!(r & bit)) {
                        const float2 a0 = a[r], a1 = a[r | bit];
                        const float xr0 = c * a0.x - s * a1.x;
                        const float xi0 = c * a0.y - s * a1.y;
                        const float xr1 = s * a0.x + c * a1.x;
                        const float xi1 = s * a0.y + c * a1.y;
                        a[r]       = make_float2(zc * xr0 + zs * xi0, zc * xi0 - zs * xr0);
                        a[r | bit] = make_float2(zc * xr1 - zs * xi1, zc * xi1 + zs * xr1);
                    }
                }
            } else {
                const int lm = 1 << (p - 3);
                const bool hi = (lane & lm) != 0;
                const float zss = hi ? -zs : zs;
#pragma unroll
                for (int r = 0; r < 8; r++) {
                    const float ox = __shfl_xor_sync(0xffffffffu, a[r].x, lm);
                    const float oy = __shfl_xor_sync(0xffffffffu, a[r].y, lm);
                    const float xr = hi ? (s * ox + c * a[r].x) : (c * a[r].x - s * ox);
                    const float xi = hi ? (s * oy + c * a[r].y) : (c * a[r].y - s * oy);
                    a[r] = make_float2(zc * xr + zss * xi, zc * xi - zss * xr);
                }
            }
        }
#pragma unroll
        for (int q = 0; q < 8; q++) {
            const int cp = 7 - q, tp = 7 - ((q + 1) & 7);
            if (cp >= 3 && tp >= 3) {
                const int cl = 1 << (cp - 3), tl = 1 << (tp - 3);
#pragma unroll
                for (int r = 0; r < 8; r++) {
                    const float ox = __shfl_xor_sync(0xffffffffu, a[r].x, tl);
                    const float oy = __shfl_xor_sync(0xffffffffu, a[r].y, tl);
                    if (lane & cl) { a[r].x = ox; a[r].y = oy; }
                }
            } else if (cp >= 3) {
                const int cl = 1 << (cp - 3), tb = 1 << tp;
                if (lane & cl) {
#pragma unroll
                    for (int r = 0; r < 8; r++) {
                        if (!(r & tb)) {
                            const float2 tmp = a[r]; a[r] = a[r | tb]; a[r | tb] = tmp;
                        }
                    }
                }
            } else if (tp >= 3) {
                const int cb = 1 << cp, tl = 1 << (tp - 3);
#pragma unroll
                for (int r = 0; r < 8; r++) {
                    const float ox = __shfl_xor_sync(0xffffffffu, a[r].x, tl);
                    const float oy = __shfl_xor_sync(0xffffffffu, a[r].y, tl);
                    if (r & cb) { a[r].x = ox; a[r].y = oy; }
                }
            } else {
                const int cb = 1 << cp, tb = 1 << tp;
#pragma unroll
                for (int r = 0; r < 8; r++) {
                    if ((r & cb) && !(r & tb)) {
                        const float2 tmp = a[r]; a[r] = a[r | tb]; a[r | tb] = tmp;
                    }
                }
            }
        }
    }

    const int pc = __popc(k) & 3;
#pragma unroll
    for (int r = 0; r < 8; r++) {
        const float2 u = a[r];
        float2 vv;
        if      (pc == 0) vv = u;
        else if (pc == 1) vv = make_float2( u.y, -u.x);
        else if (pc == 2) vv = make_float2(-u.x, -u.y);
        else              vv = make_float2(-u.y,  u.x);
        const int n2 = (lane * 8 + r) * 2;
        *(__half2*)&tr[warp][n2] = __floats2half2_rn(vv.x, vv.y);
    }
    __syncthreads();

    const int kb = blockIdx.x * 8;
#pragma unroll
    for (int i = 0; i < 2; i++) {
        const int n2 = 2 * t + i;
        __half tmp[8];
#pragma unroll
        for (int kk = 0; kk < 8; kk++) tmp[kk] = tr[kk][n2];
        *(uint4*)&g_Vn2k[n2 * 256 + kb] = *(uint4*)tmp;
    }
}

// ---------------------------------------------------------------------------
// helpers
// ---------------------------------------------------------------------------
__device__ __forceinline__ uint32_t smem_u32(const void* p) {
    return (uint32_t)__cvta_generic_to_shared(p);
}
__device__ __forceinline__ void cp_async16(uint32_t dst, const void* src) {
    asm volatile("cp.async.cg.shared.global [%0], [%1], 16;" :: "r"(dst), "l"(src));
}
__device__ __forceinline__ void ldsm4(uint32_t r[4], uint32_t addr) {
    asm volatile("ldmatrix.sync.aligned.m8n8.x4.shared.b16 {%0,%1,%2,%3}, [%4];"
                 : "=r"(r[0]), "=r"(r[1]), "=r"(r[2]), "=r"(r[3]) : "r"(addr));
}
__device__ __forceinline__ void mma16816(float4& c, const uint32_t a[4],
                                         uint32_t b0, uint32_t b1) {
    asm volatile(
        "mma.sync.aligned.m16n8k16.row.col.f32.f16.f16.f32 "
        "{%0,%1,%2,%3}, {%4,%5,%6,%7}, {%8,%9}, {%0,%1,%2,%3};"
        : "+f"(c.x), "+f"(c.y), "+f"(c.z), "+f"(c.w)
        : "r"(a[0]), "r"(a[1]), "r"(a[2]), "r"(a[3]), "r"(b0), "r"(b1));
}
__device__ __forceinline__ float red4(float v) {
    v += __shfl_xor_sync(0xffffffffu, v, 1);
    v += __shfl_xor_sync(0xffffffffu, v, 2);
    return v;
}

// ---------------------------------------------------------------------------
// Kernel 2: persistent GEMM, 2 CTAs/SM. CTA = 128 threads (4 warps),
// owns one N-quarter (B = 128 n2-rows, resident). Sample tile = 64.
// Warp tile 32 samples x 64 n2. Register-double-buffered K loop.
// ---------------------------------------------------------------------------
__global__ __launch_bounds__(THREADS)
void qsim_main_kernel(const float* __restrict__ x, float* __restrict__ out) {
    extern __shared__ __align__(16) char smem[];
    __half* m_sm = (__half*)smem;
    float*  comb = (float*)smem;            // overlay: [2][64][8] floats = 4 KB

    const int t = threadIdx.x;
    const int warp = t >> 5, lane = t & 31;
    const int quarter = blockIdx.x & 3;
    const int idx0 = blockIdx.x >> 2;       // 0..73

    // ---- stage this CTA's B quarter (128 n2-rows x 512B) once ----
    {
        const char* src = (const char*)g_Vn2k + quarter * (128 * 512);
        const uint32_t dst = smem_u32(smem + B_OFF);
#pragma unroll
        for (int i = 0; i < 32; i++) {
            const int e = t + THREADS * i;          // 4096 x 16B
            const int row = e >> 5, c16 = e & 31;
            cp_async16(dst + row * (STRIDE * 2) + c16 * 16,
                       src + row * 512 + c16 * 16);
        }
        asm volatile("cp.async.commit_group;" ::: "memory");
    }

    const uint32_t m_u = smem_u32(m_sm);
    const uint32_t b_u = smem_u32(smem + B_OFF);

    const int mh = warp >> 1;         // 32-sample half of the tile
    const int nq = warp & 1;          // 64-n2 chunk (32 amplitudes)
    const int gid = lane >> 2, tig = lane & 3;

    const int rowA_off = (mh * 32 + (lane & 7) + 8 * ((lane >> 3) & 1)) * STRIDE
                       + 8 * (lane >> 4);
    const int rowB_off = (nq * 64 + ((lane >> 4) & 1) * 8 + (lane & 7)) * STRIDE
                       + 8 * ((lane >> 3) & 1);

    const int s_mine  = t >> 1;       // sample row this thread builds (0..63)
    const int kg_mine = t & 1;        // which 128-k half this thread builds

    bool first = true;
    for (int tile = idx0; tile < NTILES; tile += NPERQ) {
        // prefetch angles for this tile (two threads share one sample row)
        float xv[8];
        {
            const float* xp = x + (size_t)(tile * TILE_M + s_mine) * NQ;
#pragma unroll
            for (int q = 0; q < 8; q++) xv[q] = xp[q];
        }
        __syncthreads();              // prior epilogue done with comb/m region

        // ---- build m tile: thread t -> sample s_mine, k in [kg*128, kg*128+128) ----
        {
            float c[8], sn[8];
#pragma unroll
            for (int q = 0; q < 8; q++) {
                float sv, cv;
                __sincosf(0.5f * xv[q], &sv, &cv);
                c[q] = cv; sn[q] = sv;
            }
            float H16[16], L16[16];
#pragma unroll
            for (int h = 0; h < 16; h++)
                H16[h] = ((h & 8) ? sn[0] : c[0]) * ((h & 4) ? sn[1] : c[1])
                       * ((h & 2) ? sn[2] : c[2]) * ((h & 1) ? sn[3] : c[3]);
#pragma unroll
            for (int v = 0; v < 16; v++)
                L16[v] = ((v & 8) ? sn[4] : c[4]) * ((v & 4) ? sn[5] : c[5])
                       * ((v & 2) ? sn[6] : c[6]) * ((v & 1) ? sn[7] : c[7]);
            __half* mrow = m_sm + s_mine * STRIDE + kg_mine * 128;
            const int kbase = kg_mine * 128;
#pragma unroll
            for (int kk = 0; kk < 128; kk += 8) {
                const float hh = H16[(kbase + kk) >> 4];
                __half tmp[8];
#pragma unroll
                for (int e = 0; e < 8; e += 2) {
                    const __half2 h2 = __floats2half2_rn(hh * L16[(kk + e) & 15],
                                                         hh * L16[(kk + e + 1) & 15]);
                    *(__half2*)&tmp[e] = h2;
                }
                *(uint4*)(mrow + kk) = *(uint4*)tmp;
            }
        }
        if (first) { asm volatile("cp.async.wait_group 0;" ::: "memory"); first = false; }
        __syncthreads();

        // ---- K=256 mma loop, register double-buffered ----
        float4 acc[2][8];
#pragma unroll
        for (int ms = 0; ms < 2; ms++)
#pragma unroll
            for (int nt = 0; nt < 8; nt++)
                acc[ms][nt] = make_float4(0.f, 0.f, 0.f, 0.f);

        uint32_t aF[2][2][4], bF[2][4][4];
#pragma unroll
        for (int ms = 0; ms < 2; ms++)
            ldsm4(aF[0][ms], m_u + (uint32_t)(rowA_off + ms * 16 * STRIDE) * 2u);
#pragma unroll
        for (int j = 0; j < 4; j++)
            ldsm4(bF[0][j], b_u + (uint32_t)(rowB_off + j * 16 * STRIDE) * 2u);

#pragma unroll
        for (int it = 0; it < 16; it++) {
            const int p = it & 1;
            if (it < 15) {
                const int kb = (it + 1) * 16;
#pragma unroll
                for (int ms = 0; ms < 2; ms++)
                    ldsm4(aF[p ^ 1][ms],
                          m_u + (uint32_t)(rowA_off + ms * 16 * STRIDE + kb) * 2u);
#pragma unroll
                for (int j = 0; j < 4; j++)
                    ldsm4(bF[p ^ 1][j],
                          b_u + (uint32_t)(rowB_off + j * 16 * STRIDE + kb) * 2u);
            }
#pragma unroll
            for (int ms = 0; ms < 2; ms++) {
#pragma unroll
                for (int j = 0; j < 4; j++) {
                    mma16816(acc[ms][2 * j],     aF[p][ms], bF[p][j][0], bF[p][j][1]);
                    mma16816(acc[ms][2 * j + 1], aF[p][ms], bF[p][j][2], bF[p][j][3]);
                }
            }
        }

        // ---- epilogue: T/S partial sums, 12 reductions per ms ----
        __syncthreads();              // all warps done reading m_sm
#pragma unroll
        for (int ms = 0; ms < 2; ms++) {
            float Tlo = 0.f, S2lo = 0.f, S1lo = 0.f, S0lo = 0.f;
            float Thi = 0.f, S2hi = 0.f, S1hi = 0.f, S0hi = 0.f;
#pragma unroll
            for (int nt = 0; nt < 8; nt++) {
                const float4 cc = acc[ms][nt];
                const float plo = cc.x * cc.x + cc.y * cc.y;
                const float phi = cc.z * cc.z + cc.w * cc.w;
                Tlo += plo; Thi += phi;
                if (nt & 4) { S2lo += plo; S2hi += phi; }
                if (nt & 2) { S1lo += plo; S1hi += phi; }
                if (nt & 1) { S0lo += plo; S0hi += phi; }
            }
            // per-lane signed copies for tig-dependent qubits (bits 1,0 of n)
            float T6lo = (tig & 2) ? -Tlo : Tlo;
            float T7lo = (tig & 1) ? -Tlo : Tlo;
            float T6hi = (tig & 2) ? -Thi : Thi;
            float T7hi = (tig & 1) ? -Thi : Thi;

            const float rT   = red4(Tlo),  rT_h  = red4(Thi);
            const float rS2  = red4(S2lo), rS2h  = red4(S2hi);
            const float rS1  = red4(S1lo), rS1h  = red4(S1hi);
            const float rS0  = red4(S0lo), rS0h  = red4(S0hi);
            const float rT6  = red4(T6lo), rT6h  = red4(T6hi);
            const float rT7  = red4(T7lo), rT7h  = red4(T7hi);

            if (tig == 0) {
                const float s0 = (quarter & 2) ? -1.f : 1.f;  // n bit7 -> q0
                const float s1 = (quarter & 1) ? -1.f : 1.f;  // n bit6 -> q1
                const float s2 = nq ? -1.f : 1.f;             // n bit5 -> q2
                const int rlo = mh * 32 + ms * 16 + gid;
                float* plo = comb + (nq * 64 + rlo) * 8;
                plo[0] = s0 * rT;  plo[1] = s1 * rT;  plo[2] = s2 * rT;
                plo[3] = rT - 2.f * rS2;
                plo[4] = rT - 2.f * rS1;
                plo[5] = rT - 2.f * rS0;
                plo[6] = rT6;      plo[7] = rT7;
                float* phi = comb + (nq * 64 + rlo + 8) * 8;
                phi[0] = s0 * rT_h; phi[1] = s1 * rT_h; phi[2] = s2 * rT_h;
                phi[3] = rT_h - 2.f * rS2h;
                phi[4] = rT_h - 2.f * rS1h;
                phi[5] = rT_h - 2.f * rS0h;
                phi[6] = rT6h;      phi[7] = rT7h;
            }
        }
        __syncthreads();

        // ---- merge nq halves, atomicAdd into out (4 quarters converge) ----
        {
            const int rr = t >> 1, qp = (t & 1) * 4;
            const float* c0 = comb + rr * 8 + qp;
            const float* c1 = comb + (64 + rr) * 8 + qp;
            float* op = out + (size_t)(tile * TILE_M + rr) * NQ + qp;
            atomicAdd(op,     c0[0] + c1[0]);
            atomicAdd(op + 1, c0[1] + c1[1]);
            atomicAdd(op + 2, c0[2] + c1[2]);
            atomicAdd(op + 3, c0[3] + c1[3]);
        }
    }
}

// ---------------------------------------------------------------------------
extern "C" void kernel_launch(void* const* d_in, const int* in_sizes, int n_in,
                              void* d_out, int out_size) {
    const float* x = (const float*)d_in[0];
    const float* w = (const float*)d_in[1];
    if (n_in >= 2 && in_sizes[0] < in_sizes[1]) {
        const float* tmp = x; x = w; w = tmp;
    }
    float* out = (float*)d_out;

    cudaFuncSetAttribute(qsim_main_kernel,
                         cudaFuncAttributeMaxDynamicSharedMemorySize, SMEM_TOTAL);

    build_V_kernel<<<544, 256>>>(w, (float4*)out);
    qsim_main_kernel<<<4 * NPERQ, THREADS, SMEM_TOTAL>>>(x, out);
}